// round 2
// baseline (speedup 1.0000x reference)
#include <cuda_runtime.h>
#include <math.h>

// ---------------- problem constants ----------------
#define MAXN   100000
#define DIM    128
#define HID    256

// ---------------- scratch (static device memory; no allocation) ----------------
__device__ __align__(128) float g_xi    [(size_t)MAXN * DIM];
__device__ __align__(128) float g_aggsum[(size_t)MAXN * DIM];
__device__ __align__(128) float g_aggmax[(size_t)MAXN * DIM];
__device__ __align__(128) float g_gi    [(size_t)MAXN * 3 * DIM];
__device__ __align__(128) float g_gh    [(size_t)MAXN * 3 * DIM];
__device__ __align__(128) float g_rnn   [(size_t)MAXN * DIM];
__device__ __align__(128) float g_h     [(size_t)MAXN * DIM];
__device__ __align__(128) float g_t1    [(size_t)MAXN * HID];
__device__ __align__(128) float g_stats [1024];   // [0:128) colsum, [128:256) colsumsq, [256:384) scale, [384:512) shift

// ---------------- init ----------------
__global__ void init_kernel(size_t n) {
    size_t i = (size_t)blockIdx.x * blockDim.x + threadIdx.x;
    size_t stride = (size_t)gridDim.x * blockDim.x;
    unsigned* mx = reinterpret_cast<unsigned*>(g_aggmax);
    for (size_t k = i; k < n; k += stride) {
        g_aggsum[k] = 0.f;
        mx[k] = 0xFF800000u;   // -inf
    }
    if (i < 1024) g_stats[i] = 0.f;
}

// ---------------- SGEMM: C[m,n] = sum_k A[m,k]*W[n,k] (+bias)(+C)(+eps*extra)(relu) ----------------
// A: M x K (lda), W: N x K row-major (ldw), C: M x N (ldc). BM=BN=128, BK=8, 256 threads, 8x8/thread.
template<bool ACCUM, bool RELU, bool BIAS, bool EXTRA>
__global__ __launch_bounds__(256)
void sgemm_tn(const float* __restrict__ A, int lda,
              const float* __restrict__ W, int ldw,
              const float* __restrict__ bias,
              const float* __restrict__ extra,
              const float* __restrict__ epsp,
              float* __restrict__ C, int ldc,
              int M, int K)
{
    __shared__ float As[8][128];
    __shared__ float Ws[8][128];

    const int tid = threadIdx.x;
    const int bm  = blockIdx.x * 128;
    const int bn  = blockIdx.y * 128;

    const int tr = tid >> 4;         // 0..15
    const int tc = tid & 15;         // 0..15

    const int lrow = tid >> 1;       // 0..127
    const int lcol = (tid & 1) * 4;  // 0 or 4
    const int am = bm + lrow;
    const int wn = bn + lrow;

    float acc[8][8];
#pragma unroll
    for (int i = 0; i < 8; i++)
#pragma unroll
        for (int j = 0; j < 8; j++) acc[i][j] = 0.f;

    for (int kb = 0; kb < K; kb += 8) {
        float4 av = make_float4(0.f, 0.f, 0.f, 0.f);
        if (am < M)
            av = *reinterpret_cast<const float4*>(A + (size_t)am * lda + kb + lcol);
        float4 wv = *reinterpret_cast<const float4*>(W + (size_t)wn * ldw + kb + lcol);

        As[lcol + 0][lrow] = av.x; As[lcol + 1][lrow] = av.y;
        As[lcol + 2][lrow] = av.z; As[lcol + 3][lrow] = av.w;
        Ws[lcol + 0][lrow] = wv.x; Ws[lcol + 1][lrow] = wv.y;
        Ws[lcol + 2][lrow] = wv.z; Ws[lcol + 3][lrow] = wv.w;
        __syncthreads();

#pragma unroll
        for (int k = 0; k < 8; k++) {
            float rm[8], rn[8];
#pragma unroll
            for (int i = 0; i < 8; i++) rm[i] = As[k][tr * 8 + i];
#pragma unroll
            for (int j = 0; j < 8; j++) rn[j] = Ws[k][tc * 8 + j];
#pragma unroll
            for (int i = 0; i < 8; i++)
#pragma unroll
                for (int j = 0; j < 8; j++) acc[i][j] = fmaf(rm[i], rn[j], acc[i][j]);
        }
        __syncthreads();
    }

    const float epsv = EXTRA ? *epsp : 0.f;
#pragma unroll
    for (int i = 0; i < 8; i++) {
        const int m = bm + tr * 8 + i;
        if (m < M) {
#pragma unroll
            for (int j = 0; j < 8; j++) {
                const int n = bn + tc * 8 + j;
                float v = acc[i][j];
                if (BIAS)  v += bias[n];
                if (ACCUM) v += C[(size_t)m * ldc + n];
                if (EXTRA) v += epsv * extra[(size_t)m * ldc + n];
                if (RELU)  v = fmaxf(v, 0.f);
                C[(size_t)m * ldc + n] = v;
            }
        }
    }
}

// ---------------- edge scatter (sum + max), one warp per edge ----------------
__device__ __forceinline__ void atomicMaxF(float* addr, float v) {
    if (v >= 0.f) atomicMax(reinterpret_cast<int*>(addr), __float_as_int(v));
    else          atomicMin(reinterpret_cast<unsigned*>(addr), __float_as_uint(v));
}

__global__ __launch_bounds__(256)
void edge_scatter(const float* __restrict__ x, const int* __restrict__ edges, int E)
{
    const int gw   = (blockIdx.x * blockDim.x + threadIdx.x) >> 5;
    const int lane = threadIdx.x & 31;
    if (gw >= E) return;
    const int s = __ldg(edges + gw);
    const int t = __ldg(edges + E + gw);
    const size_t so = (size_t)s * DIM + lane * 4;
    const size_t to = (size_t)t * DIM + lane * 4;
    const float4 vs = *reinterpret_cast<const float4*>(x    + so);
    const float4 vm = *reinterpret_cast<const float4*>(g_xi + so);
    atomicAdd(g_aggsum + to + 0, vs.x);
    atomicAdd(g_aggsum + to + 1, vs.y);
    atomicAdd(g_aggsum + to + 2, vs.z);
    atomicAdd(g_aggsum + to + 3, vs.w);
    atomicMaxF(g_aggmax + to + 0, vm.x);
    atomicMaxF(g_aggmax + to + 1, vm.y);
    atomicMaxF(g_aggmax + to + 2, vm.z);
    atomicMaxF(g_aggmax + to + 3, vm.w);
}

// ---------------- sanitize empty segments: -inf -> 0 ----------------
__global__ void fix_max(size_t n) {
    size_t i = (size_t)blockIdx.x * blockDim.x + threadIdx.x;
    if (i < n) {
        float v = g_aggmax[i];
        if (!isfinite(v)) g_aggmax[i] = 0.f;
    }
}

// ---------------- GRU elementwise ----------------
__global__ void gru_kernel(const float* __restrict__ x, int M) {
    const size_t i = (size_t)blockIdx.x * blockDim.x + threadIdx.x;
    if (i >= (size_t)M * DIM) return;
    const size_t m = i >> 7;
    const int    d = (int)(i & 127);
    const size_t b = m * (3 * DIM);
    const float ir = g_gi[b + d],       hr = g_gh[b + d];
    const float iz = g_gi[b + DIM + d], hz = g_gh[b + DIM + d];
    const float in = g_gi[b + 2*DIM + d], hn = g_gh[b + 2*DIM + d];
    const float r  = 1.f / (1.f + __expf(-(ir + hr)));
    const float z  = 1.f / (1.f + __expf(-(iz + hz)));
    const float nc = tanhf(in + r * hn);
    g_rnn[i] = (1.f - z) * nc + z * x[i];
}

// ---------------- batchnorm ----------------
__global__ void bn_stats(const float* __restrict__ out, int M) {
    const int c = threadIdx.x;   // 128 threads
    float s = 0.f, s2 = 0.f;
    for (int m = blockIdx.x; m < M; m += gridDim.x) {
        float v = out[(size_t)m * DIM + c];
        s += v; s2 += v * v;
    }
    atomicAdd(&g_stats[c], s);
    atomicAdd(&g_stats[128 + c], s2);
}

__global__ void bn_finalize(const float* __restrict__ gamma, const float* __restrict__ beta, int M) {
    const int c = threadIdx.x;   // 128 threads, 1 block
    const float invM = 1.f / (float)M;
    const float mean = g_stats[c] * invM;
    const float var  = g_stats[128 + c] * invM - mean * mean;
    const float sc   = gamma[c] * rsqrtf(var + 1e-5f);
    g_stats[256 + c] = sc;
    g_stats[384 + c] = beta[c] - mean * sc;
}

__global__ void bn_apply(float* __restrict__ out, int M) {
    const size_t i = (size_t)blockIdx.x * blockDim.x + threadIdx.x;
    if (i >= (size_t)M * DIM) return;
    const int c = (int)(i & 127);
    out[i] = out[i] * g_stats[256 + c] + g_stats[384 + c];
}

// ---------------- launcher ----------------
extern "C" void kernel_launch(void* const* d_in, const int* in_sizes, int n_in,
                              void* d_out, int out_size)
{
    const float* x       = (const float*)d_in[0];
    const int*   edges   = (const int*)  d_in[1];
    const float* W_aff   = (const float*)d_in[2];
    const float* b_aff   = (const float*)d_in[3];
    const float* W_ih    = (const float*)d_in[4];
    const float* b_ih    = (const float*)d_in[5];
    const float* W_hh    = (const float*)d_in[6];
    const float* b_hh    = (const float*)d_in[7];
    const float* W_merge = (const float*)d_in[8];
    const float* b_merge = (const float*)d_in[9];
    const float* epsp    = (const float*)d_in[10];
    const float* W1      = (const float*)d_in[11];
    const float* b1      = (const float*)d_in[12];
    const float* W2      = (const float*)d_in[13];
    const float* b2      = (const float*)d_in[14];
    const float* gamma   = (const float*)d_in[15];
    const float* beta    = (const float*)d_in[16];
    float* out = (float*)d_out;

    const int M = in_sizes[0] / DIM;
    const int E = in_sizes[1] / 2;
    const size_t ND = (size_t)M * DIM;

    void *p_xi, *p_sum, *p_max, *p_gi, *p_gh, *p_rnn, *p_h, *p_t1;
    cudaGetSymbolAddress(&p_xi,  g_xi);
    cudaGetSymbolAddress(&p_sum, g_aggsum);
    cudaGetSymbolAddress(&p_max, g_aggmax);
    cudaGetSymbolAddress(&p_gi,  g_gi);
    cudaGetSymbolAddress(&p_gh,  g_gh);
    cudaGetSymbolAddress(&p_rnn, g_rnn);
    cudaGetSymbolAddress(&p_h,   g_h);
    cudaGetSymbolAddress(&p_t1,  g_t1);
    float* xi  = (float*)p_xi;   float* aggsum = (float*)p_sum;
    float* aggmax = (float*)p_max;
    float* gi  = (float*)p_gi;   float* gh  = (float*)p_gh;
    float* rnn = (float*)p_rnn;  float* h   = (float*)p_h;
    float* t1  = (float*)p_t1;

    const int mtiles = (M + 127) / 128;
    const int ew     = (int)(((size_t)E * 32 + 255) / 256);
    const int nd_blk = (int)((ND + 255) / 256);

    // 1) init agg buffers + stats
    init_kernel<<<2048, 256>>>(ND);

    // 2) xi = x @ W_aff^T + b_aff
    sgemm_tn<false,false,true,false><<<dim3(mtiles,1), 256>>>(
        x, DIM, W_aff, DIM, b_aff, nullptr, nullptr, xi, DIM, M, DIM);

    // 3) edge scatter: agg_sum += x[src]; agg_max = max(xi[src])
    edge_scatter<<<ew, 256>>>(x, edges, E);

    // 4) -inf -> 0
    fix_max<<<nd_blk, 256>>>(ND);

    // 5) gi = agg_max @ W_ih^T + b_ih   (N = 384)
    sgemm_tn<false,false,true,false><<<dim3(mtiles,3), 256>>>(
        aggmax, DIM, W_ih, DIM, b_ih, nullptr, nullptr, gi, 3*DIM, M, DIM);

    // 6) gh = x @ W_hh^T + b_hh         (N = 384)
    sgemm_tn<false,false,true,false><<<dim3(mtiles,3), 256>>>(
        x, DIM, W_hh, DIM, b_hh, nullptr, nullptr, gh, 3*DIM, M, DIM);

    // 7) GRU elementwise -> rnn
    gru_kernel<<<nd_blk, 256>>>(x, M);

    // 8) h = agg_sum @ W_merge[:, :128]^T
    sgemm_tn<false,false,false,false><<<dim3(mtiles,1), 256>>>(
        aggsum, DIM, W_merge, 2*DIM, nullptr, nullptr, nullptr, h, DIM, M, DIM);

    // 9) h += rnn @ W_merge[:, 128:]^T + b_merge + eps * x
    sgemm_tn<true,false,true,true><<<dim3(mtiles,1), 256>>>(
        rnn, DIM, W_merge + DIM, 2*DIM, b_merge, x, epsp, h, DIM, M, DIM);

    // 10) t1 = relu(h @ W1^T + b1)      (N = 256)
    sgemm_tn<false,true,true,false><<<dim3(mtiles,2), 256>>>(
        h, DIM, W1, DIM, b1, nullptr, nullptr, t1, HID, M, DIM);

    // 11) out = relu(t1 @ W2^T + b2)    (K = 256)
    sgemm_tn<false,true,true,false><<<dim3(mtiles,1), 256>>>(
        t1, HID, W2, HID, b2, nullptr, nullptr, out, DIM, M, HID);

    // 12-14) batchnorm (train mode, biased variance)
    bn_stats<<<512, 128>>>(out, M);
    bn_finalize<<<1, 128>>>(gamma, beta, M);
    bn_apply<<<nd_blk, 256>>>(out, M);
}

// round 4
// speedup vs baseline: 1.3514x; 1.3514x over previous
#include <cuda_runtime.h>
#include <cuda_bf16.h>
#include <cstdint>
#include <math.h>

// ---------------- problem constants ----------------
#define MAXN   100000
#define DIM    128
#define HID    256

// ---------------- scratch (static device memory; no allocation) ----------------
__device__ __align__(128) float g_xi    [(size_t)MAXN * DIM];
__device__ __align__(128) float g_aggsum[(size_t)MAXN * DIM];
__device__ __align__(128) float g_aggmax[(size_t)MAXN * DIM];
__device__ __align__(128) float g_gi    [(size_t)MAXN * 3 * DIM];
__device__ __align__(128) float g_gh    [(size_t)MAXN * 3 * DIM];
__device__ __align__(128) float g_rnn   [(size_t)MAXN * DIM];
__device__ __align__(128) float g_h     [(size_t)MAXN * DIM];
__device__ __align__(128) float g_t1    [(size_t)MAXN * HID];
__device__ __align__(128) float g_stats [1024];

// ================= warp-mma helpers (baseline PTX: ldmatrix + mma.sync bf16) =================
__device__ __forceinline__ uint32_t smem_u32(const void* p) {
    uint32_t a;
    asm("{ .reg .u64 t; cvta.to.shared.u64 t, %1; cvt.u32.u64 %0, t; }" : "=r"(a) : "l"(p));
    return a;
}

__device__ __forceinline__ void ldsm_x4(uint32_t& r0, uint32_t& r1, uint32_t& r2, uint32_t& r3,
                                        uint32_t addr) {
    asm volatile("ldmatrix.sync.aligned.m8n8.x4.shared.b16 {%0,%1,%2,%3}, [%4];"
                 : "=r"(r0), "=r"(r1), "=r"(r2), "=r"(r3) : "r"(addr));
}

__device__ __forceinline__ void mma_bf16(float* c, const uint32_t* a, uint32_t b0, uint32_t b1) {
    asm volatile(
        "mma.sync.aligned.m16n8k16.row.col.f32.bf16.bf16.f32 "
        "{%0,%1,%2,%3}, {%4,%5,%6,%7}, {%8,%9}, {%0,%1,%2,%3};"
        : "+f"(c[0]), "+f"(c[1]), "+f"(c[2]), "+f"(c[3])
        : "r"(a[0]), "r"(a[1]), "r"(a[2]), "r"(a[3]), "r"(b0), "r"(b1));
}

// ---------------- smem layout: 4 bf16 tiles of 128 x 128, padded row stride ----------------
#define SROW      136                      // bf16 elements per row (128 + 8 pad)
#define TILE_B    (128 * SROW * 2)         // 34816 bytes
#define OFF_AHI   0
#define OFF_ALO   (TILE_B)
#define OFF_WHI   (2 * TILE_B)
#define OFF_WLO   (3 * TILE_B)
#define TCG_SMEM  (4 * TILE_B)             // 139264 bytes

__device__ __forceinline__ void split_store(char* smem, uint32_t off_hi, uint32_t off_lo, float4 v) {
    __nv_bfloat162 h0 = __floats2bfloat162_rn(v.x, v.y);
    __nv_bfloat162 h1 = __floats2bfloat162_rn(v.z, v.w);
    float r0 = v.x - __bfloat162float(h0.x);
    float r1 = v.y - __bfloat162float(h0.y);
    float r2 = v.z - __bfloat162float(h1.x);
    float r3 = v.w - __bfloat162float(h1.y);
    __nv_bfloat162 l0 = __floats2bfloat162_rn(r0, r1);
    __nv_bfloat162 l1 = __floats2bfloat162_rn(r2, r3);
    *reinterpret_cast<uint2*>(smem + off_hi) =
        make_uint2(*reinterpret_cast<const uint32_t*>(&h0), *reinterpret_cast<const uint32_t*>(&h1));
    *reinterpret_cast<uint2*>(smem + off_lo) =
        make_uint2(*reinterpret_cast<const uint32_t*>(&l0), *reinterpret_cast<const uint32_t*>(&l1));
}

// ---------------- tensor GEMM: C[m,n] = sum_k A[m,k] * W[n,k]  (split-bf16, fp32 acc) ----------------
// CTA tile 128x128, 8 warps in 2(m) x 4(n), warp tile 64x32. K consumed in chunks of 128.
template<bool ACCUM, bool RELU, bool BIAS, bool EXTRA, bool SAN>
__global__ __launch_bounds__(256, 1)
void tc_gemm(const float* __restrict__ A, int lda,
             const float* __restrict__ W, int ldw,
             const float* __restrict__ bias,
             const float* __restrict__ extra,
             const float* __restrict__ epsp,
             float* __restrict__ C, int ldc, int M, int K)
{
    extern __shared__ char smem[];
    const uint32_t sb = smem_u32(smem);
    const int tid  = threadIdx.x;
    const int wid  = tid >> 5;
    const int lane = tid & 31;
    const int bm   = blockIdx.x * 128;
    const int bn   = blockIdx.y * 128;
    const int wm   = (wid >> 2) * 64;   // warp row offset in CTA tile
    const int wn   = (wid & 3) * 32;    // warp col offset in CTA tile

    float acc[4][4][4];                 // [mi][nj][frag]
#pragma unroll
    for (int i = 0; i < 4; i++)
#pragma unroll
        for (int j = 0; j < 4; j++)
#pragma unroll
            for (int f = 0; f < 4; f++) acc[i][j][f] = 0.f;

    // ldmatrix per-lane base offsets (bf16-element units)
    const int g  = lane >> 3;           // address group 0..3
    const int lr = lane & 7;
    // A frags: groups = (rows +0/+8) x (k +0/+8):  row = wm + i*16 + (g&1)*8 + lr, k = (g>>1)*8
    const uint32_t aRowPart = (uint32_t)((wm + (g & 1) * 8 + lr) * SROW + (g >> 1) * 8);
    // B frags: groups = (n j*8 .. ) x (k +0/+8):  row = wn + (g>>1)*8 + lr, k = (g&1)*8
    const uint32_t bRowPart = (uint32_t)((wn + (g >> 1) * 8 + lr) * SROW + (g & 1) * 8);

    for (int kb = 0; kb < K; kb += 128) {
        if (kb) __syncthreads();
        // ---- load 128x128 fp32 chunks of A and W, convert to bf16 hi/lo tiles ----
#pragma unroll 4
        for (int it = tid; it < 4096; it += 256) {
            const int r = it >> 5;
            const int c = (it & 31) << 2;
            const uint32_t off = (uint32_t)(r * SROW + c) * 2;
            float4 va = make_float4(0.f, 0.f, 0.f, 0.f);
            const int am = bm + r;
            if (am < M) va = *reinterpret_cast<const float4*>(A + (size_t)am * lda + kb + c);
            if (SAN) {
                if (!isfinite(va.x)) va.x = 0.f;
                if (!isfinite(va.y)) va.y = 0.f;
                if (!isfinite(va.z)) va.z = 0.f;
                if (!isfinite(va.w)) va.w = 0.f;
            }
            split_store(smem, OFF_AHI + off, OFF_ALO + off, va);
            const float4 vw = *reinterpret_cast<const float4*>(W + (size_t)(bn + r) * ldw + kb + c);
            split_store(smem, OFF_WHI + off, OFF_WLO + off, vw);
        }
        __syncthreads();

        // ---- 8 k-steps of 16, three split passes each ----
#pragma unroll
        for (int ks = 0; ks < 8; ks++) {
            const uint32_t kk = ks * 16;
            uint32_t ah[4][4], al[4][4];
            uint32_t bh[4][2], bl[4][2];
            // A hi/lo fragments (4 m-tiles)
#pragma unroll
            for (int i = 0; i < 4; i++) {
                const uint32_t ao = (aRowPart + (uint32_t)(i * 16) * SROW + kk) * 2;
                ldsm_x4(ah[i][0], ah[i][1], ah[i][2], ah[i][3], sb + OFF_AHI + ao);
                ldsm_x4(al[i][0], al[i][1], al[i][2], al[i][3], sb + OFF_ALO + ao);
            }
            // B hi/lo fragments (4 n-tiles); x4 covers 2 n-tiles x 2 k-halves
            {
                const uint32_t bo0 = (bRowPart + kk) * 2;
                const uint32_t bo1 = (bRowPart + (uint32_t)(16 * SROW) + kk) * 2;
                ldsm_x4(bh[0][0], bh[0][1], bh[1][0], bh[1][1], sb + OFF_WHI + bo0);
                ldsm_x4(bh[2][0], bh[2][1], bh[3][0], bh[3][1], sb + OFF_WHI + bo1);
                ldsm_x4(bl[0][0], bl[0][1], bl[1][0], bl[1][1], sb + OFF_WLO + bo0);
                ldsm_x4(bl[2][0], bl[2][1], bl[3][0], bl[3][1], sb + OFF_WLO + bo1);
            }
#pragma unroll
            for (int i = 0; i < 4; i++)
#pragma unroll
                for (int j = 0; j < 4; j++) {
                    mma_bf16(acc[i][j], ah[i], bh[j][0], bh[j][1]);   // hi * hi
                    mma_bf16(acc[i][j], ah[i], bl[j][0], bl[j][1]);   // hi * lo
                    mma_bf16(acc[i][j], al[i], bh[j][0], bh[j][1]);   // lo * hi
                }
        }
    }

    // ---- epilogue: fragment mapping row = base + lane/4 (+8), col = base + 2*(lane%4) ----
    const float epsv = EXTRA ? __ldg(epsp) : 0.f;
    const int qr = lane >> 2;
    const int qc = (lane & 3) * 2;
#pragma unroll
    for (int i = 0; i < 4; i++) {
        const int r0 = bm + wm + i * 16 + qr;
        const int r1 = r0 + 8;
#pragma unroll
        for (int j = 0; j < 4; j++) {
            const int col = bn + wn + j * 8 + qc;
#pragma unroll
            for (int half = 0; half < 2; half++) {
                const int rr = half ? r1 : r0;
                if (rr < M) {
                    float vx = acc[i][j][half * 2 + 0];
                    float vy = acc[i][j][half * 2 + 1];
                    if (BIAS) {
                        const float2 b2 = *reinterpret_cast<const float2*>(bias + col);
                        vx += b2.x; vy += b2.y;
                    }
                    float* cp = C + (size_t)rr * ldc + col;
                    if (ACCUM) {
                        const float2 c2 = *reinterpret_cast<const float2*>(cp);
                        vx += c2.x; vy += c2.y;
                    }
                    if (EXTRA) {
                        const float2 e2 = *reinterpret_cast<const float2*>(extra + (size_t)rr * ldc + col);
                        vx = fmaf(epsv, e2.x, vx); vy = fmaf(epsv, e2.y, vy);
                    }
                    if (RELU) { vx = fmaxf(vx, 0.f); vy = fmaxf(vy, 0.f); }
                    *reinterpret_cast<float2*>(cp) = make_float2(vx, vy);
                }
            }
        }
    }
}

// ---------------- init ----------------
__global__ void init_kernel(size_t n) {
    size_t i = (size_t)blockIdx.x * blockDim.x + threadIdx.x;
    size_t stride = (size_t)gridDim.x * blockDim.x;
    unsigned* mx = reinterpret_cast<unsigned*>(g_aggmax);
    for (size_t k = i; k < n; k += stride) {
        g_aggsum[k] = 0.f;
        mx[k] = 0xFF800000u;   // -inf
    }
    if (i < 1024) g_stats[i] = 0.f;
}

// ---------------- edge scatter (sum + max), one warp per edge ----------------
__device__ __forceinline__ void atomicMaxF(float* addr, float v) {
    if (v >= 0.f) atomicMax(reinterpret_cast<int*>(addr), __float_as_int(v));
    else          atomicMin(reinterpret_cast<unsigned*>(addr), __float_as_uint(v));
}

__global__ __launch_bounds__(256)
void edge_scatter(const float* __restrict__ x, const int* __restrict__ edges, int E)
{
    const int gw   = (blockIdx.x * blockDim.x + threadIdx.x) >> 5;
    const int lane = threadIdx.x & 31;
    if (gw >= E) return;
    const int s = __ldg(edges + gw);
    const int t = __ldg(edges + E + gw);
    const size_t so = (size_t)s * DIM + lane * 4;
    const size_t to = (size_t)t * DIM + lane * 4;
    const float4 vs = *reinterpret_cast<const float4*>(x    + so);
    const float4 vm = *reinterpret_cast<const float4*>(g_xi + so);
    atomicAdd(g_aggsum + to + 0, vs.x);
    atomicAdd(g_aggsum + to + 1, vs.y);
    atomicAdd(g_aggsum + to + 2, vs.z);
    atomicAdd(g_aggsum + to + 3, vs.w);
    atomicMaxF(g_aggmax + to + 0, vm.x);
    atomicMaxF(g_aggmax + to + 1, vm.y);
    atomicMaxF(g_aggmax + to + 2, vm.z);
    atomicMaxF(g_aggmax + to + 3, vm.w);
}

// ---------------- GRU elementwise ----------------
__global__ void gru_kernel(const float* __restrict__ x, int M) {
    const size_t i = (size_t)blockIdx.x * blockDim.x + threadIdx.x;
    if (i >= (size_t)M * DIM) return;
    const size_t m = i >> 7;
    const int    d = (int)(i & 127);
    const size_t b = m * (3 * DIM);
    const float ir = g_gi[b + d],         hr = g_gh[b + d];
    const float iz = g_gi[b + DIM + d],   hz = g_gh[b + DIM + d];
    const float in = g_gi[b + 2*DIM + d], hn = g_gh[b + 2*DIM + d];
    const float r  = 1.f / (1.f + __expf(-(ir + hr)));
    const float z  = 1.f / (1.f + __expf(-(iz + hz)));
    const float nc = tanhf(in + r * hn);
    g_rnn[i] = (1.f - z) * nc + z * x[i];
}

// ---------------- batchnorm ----------------
__global__ void bn_stats(const float* __restrict__ out, int M) {
    const int c = threadIdx.x;   // 128 threads
    float s = 0.f, s2 = 0.f;
    for (int m = blockIdx.x; m < M; m += gridDim.x) {
        float v = out[(size_t)m * DIM + c];
        s += v; s2 += v * v;
    }
    atomicAdd(&g_stats[c], s);
    atomicAdd(&g_stats[128 + c], s2);
}

__global__ void bn_finalize(const float* __restrict__ gamma, const float* __restrict__ beta, int M) {
    const int c = threadIdx.x;   // 128 threads, 1 block
    const float invM = 1.f / (float)M;
    const float mean = g_stats[c] * invM;
    const float var  = g_stats[128 + c] * invM - mean * mean;
    const float sc   = gamma[c] * rsqrtf(var + 1e-5f);
    g_stats[256 + c] = sc;
    g_stats[384 + c] = beta[c] - mean * sc;
}

__global__ void bn_apply(float* __restrict__ out, int M) {
    const size_t i = (size_t)blockIdx.x * blockDim.x + threadIdx.x;
    if (i >= (size_t)M * DIM) return;
    const int c = (int)(i & 127);
    out[i] = out[i] * g_stats[256 + c] + g_stats[384 + c];
}

// ---------------- launcher ----------------
extern "C" void kernel_launch(void* const* d_in, const int* in_sizes, int n_in,
                              void* d_out, int out_size)
{
    const float* x       = (const float*)d_in[0];
    const int*   edges   = (const int*)  d_in[1];
    const float* W_aff   = (const float*)d_in[2];
    const float* b_aff   = (const float*)d_in[3];
    const float* W_ih    = (const float*)d_in[4];
    const float* b_ih    = (const float*)d_in[5];
    const float* W_hh    = (const float*)d_in[6];
    const float* b_hh    = (const float*)d_in[7];
    const float* W_merge = (const float*)d_in[8];
    const float* b_merge = (const float*)d_in[9];
    const float* epsp    = (const float*)d_in[10];
    const float* W1      = (const float*)d_in[11];
    const float* b1      = (const float*)d_in[12];
    const float* W2      = (const float*)d_in[13];
    const float* b2      = (const float*)d_in[14];
    const float* gamma   = (const float*)d_in[15];
    const float* beta    = (const float*)d_in[16];
    float* out = (float*)d_out;

    const int M = in_sizes[0] / DIM;
    const int E = in_sizes[1] / 2;
    const size_t ND = (size_t)M * DIM;

    void *p_xi, *p_sum, *p_max, *p_gi, *p_gh, *p_rnn, *p_h, *p_t1;
    cudaGetSymbolAddress(&p_xi,  g_xi);
    cudaGetSymbolAddress(&p_sum, g_aggsum);
    cudaGetSymbolAddress(&p_max, g_aggmax);
    cudaGetSymbolAddress(&p_gi,  g_gi);
    cudaGetSymbolAddress(&p_gh,  g_gh);
    cudaGetSymbolAddress(&p_rnn, g_rnn);
    cudaGetSymbolAddress(&p_h,   g_h);
    cudaGetSymbolAddress(&p_t1,  g_t1);
    float* xi  = (float*)p_xi;   float* aggsum = (float*)p_sum;
    float* aggmax = (float*)p_max;
    float* gi  = (float*)p_gi;   float* gh  = (float*)p_gh;
    float* rnn = (float*)p_rnn;  float* h   = (float*)p_h;
    float* t1  = (float*)p_t1;

    cudaFuncSetAttribute(tc_gemm<false,false,true, false,false>, cudaFuncAttributeMaxDynamicSharedMemorySize, TCG_SMEM);
    cudaFuncSetAttribute(tc_gemm<false,false,true, false,true >, cudaFuncAttributeMaxDynamicSharedMemorySize, TCG_SMEM);
    cudaFuncSetAttribute(tc_gemm<false,false,false,false,false>, cudaFuncAttributeMaxDynamicSharedMemorySize, TCG_SMEM);
    cudaFuncSetAttribute(tc_gemm<true, false,true, true, false>, cudaFuncAttributeMaxDynamicSharedMemorySize, TCG_SMEM);
    cudaFuncSetAttribute(tc_gemm<false,true, true, false,false>, cudaFuncAttributeMaxDynamicSharedMemorySize, TCG_SMEM);

    const int mtiles = (M + 127) / 128;
    const int ew     = (int)(((size_t)E * 32 + 255) / 256);
    const int nd_blk = (int)((ND + 255) / 256);

    // 1) init agg buffers + stats
    init_kernel<<<2048, 256>>>(ND);

    // 2) xi = x @ W_aff^T + b_aff
    tc_gemm<false,false,true,false,false><<<dim3(mtiles,1), 256, TCG_SMEM>>>(
        x, DIM, W_aff, DIM, b_aff, nullptr, nullptr, xi, DIM, M, DIM);

    // 3) edge scatter: agg_sum += x[src]; agg_max = max(xi[src])
    edge_scatter<<<ew, 256>>>(x, edges, E);

    // 4) gi = sanitize(agg_max) @ W_ih^T + b_ih   (N = 384; -inf -> 0 fused into loader)
    tc_gemm<false,false,true,false,true><<<dim3(mtiles,3), 256, TCG_SMEM>>>(
        aggmax, DIM, W_ih, DIM, b_ih, nullptr, nullptr, gi, 3*DIM, M, DIM);

    // 5) gh = x @ W_hh^T + b_hh                   (N = 384)
    tc_gemm<false,false,true,false,false><<<dim3(mtiles,3), 256, TCG_SMEM>>>(
        x, DIM, W_hh, DIM, b_hh, nullptr, nullptr, gh, 3*DIM, M, DIM);

    // 6) GRU elementwise -> rnn
    gru_kernel<<<nd_blk, 256>>>(x, M);

    // 7) h = agg_sum @ W_merge[:, :128]^T
    tc_gemm<false,false,false,false,false><<<dim3(mtiles,1), 256, TCG_SMEM>>>(
        aggsum, DIM, W_merge, 2*DIM, nullptr, nullptr, nullptr, h, DIM, M, DIM);

    // 8) h += rnn @ W_merge[:, 128:]^T + b_merge + eps * x
    tc_gemm<true,false,true,true,false><<<dim3(mtiles,1), 256, TCG_SMEM>>>(
        rnn, DIM, W_merge + DIM, 2*DIM, b_merge, x, epsp, h, DIM, M, DIM);

    // 9) t1 = relu(h @ W1^T + b1)                 (N = 256)
    tc_gemm<false,true,true,false,false><<<dim3(mtiles,2), 256, TCG_SMEM>>>(
        h, DIM, W1, DIM, b1, nullptr, nullptr, t1, HID, M, DIM);

    // 10) out = relu(t1 @ W2^T + b2)              (K = 256)
    tc_gemm<false,true,true,false,false><<<dim3(mtiles,1), 256, TCG_SMEM>>>(
        t1, HID, W2, HID, b2, nullptr, nullptr, out, DIM, M, HID);

    // 11-13) batchnorm (train mode, biased variance)
    bn_stats<<<512, 128>>>(out, M);
    bn_finalize<<<1, 128>>>(gamma, beta, M);
    bn_apply<<<nd_blk, 256>>>(out, M);
}

// round 5
// speedup vs baseline: 2.7661x; 2.0469x over previous
#include <cuda_runtime.h>
#include <cuda_bf16.h>
#include <cstdint>
#include <math.h>

// ---------------- problem constants ----------------
#define MAXN   100000
#define MAXE   1600000
#define DIM    128
#define HID    256

// ---------------- scratch (static device memory; no allocation) ----------------
__device__ __align__(128) float g_xi    [(size_t)MAXN * DIM];
__device__ __align__(128) float g_aggsum[(size_t)MAXN * DIM];
__device__ __align__(128) float g_aggmax[(size_t)MAXN * DIM];
__device__ __align__(128) float g_gi    [(size_t)MAXN * 3 * DIM];
__device__ __align__(128) float g_gh    [(size_t)MAXN * 3 * DIM];
__device__ __align__(128) float g_rnn   [(size_t)MAXN * DIM];
__device__ __align__(128) float g_h     [(size_t)MAXN * DIM];
__device__ __align__(128) float g_t1    [(size_t)MAXN * HID];
__device__ __align__(128) float g_stats [1024];
// CSR scratch
__device__ __align__(128) int   g_deg   [MAXN];
__device__ __align__(128) int   g_off   [MAXN];
__device__ __align__(128) int   g_cur   [MAXN];
__device__ __align__(128) int   g_part  [1024];
__device__ __align__(128) int   g_ssrc  [MAXE];

// ================= warp-mma helpers (baseline PTX: ldmatrix + mma.sync bf16) =================
__device__ __forceinline__ uint32_t smem_u32(const void* p) {
    uint32_t a;
    asm("{ .reg .u64 t; cvta.to.shared.u64 t, %1; cvt.u32.u64 %0, t; }" : "=r"(a) : "l"(p));
    return a;
}

__device__ __forceinline__ void ldsm_x4(uint32_t& r0, uint32_t& r1, uint32_t& r2, uint32_t& r3,
                                        uint32_t addr) {
    asm volatile("ldmatrix.sync.aligned.m8n8.x4.shared.b16 {%0,%1,%2,%3}, [%4];"
                 : "=r"(r0), "=r"(r1), "=r"(r2), "=r"(r3) : "r"(addr));
}

__device__ __forceinline__ void mma_bf16(float* c, const uint32_t* a, uint32_t b0, uint32_t b1) {
    asm volatile(
        "mma.sync.aligned.m16n8k16.row.col.f32.bf16.bf16.f32 "
        "{%0,%1,%2,%3}, {%4,%5,%6,%7}, {%8,%9}, {%0,%1,%2,%3};"
        : "+f"(c[0]), "+f"(c[1]), "+f"(c[2]), "+f"(c[3])
        : "r"(a[0]), "r"(a[1]), "r"(a[2]), "r"(a[3]), "r"(b0), "r"(b1));
}

// ---------------- smem layout: A 128xK128 hi/lo, W 64xK128 hi/lo, padded rows ----------------
#define SROW      136                      // bf16 elements per row (128 + 8 pad)
#define ATILE_B   (128 * SROW * 2)         // 34816
#define WTILE_B   (64  * SROW * 2)         // 17408
#define OFF_AHI   0
#define OFF_ALO   (ATILE_B)
#define OFF_WHI   (2 * ATILE_B)
#define OFF_WLO   (2 * ATILE_B + WTILE_B)
#define TCG_SMEM  (2 * ATILE_B + 2 * WTILE_B)   // 104448 -> 2 CTAs/SM

__device__ __forceinline__ void split_store(char* smem, uint32_t off_hi, uint32_t off_lo, float4 v) {
    __nv_bfloat162 h0 = __floats2bfloat162_rn(v.x, v.y);
    __nv_bfloat162 h1 = __floats2bfloat162_rn(v.z, v.w);
    float r0 = v.x - __bfloat162float(h0.x);
    float r1 = v.y - __bfloat162float(h0.y);
    float r2 = v.z - __bfloat162float(h1.x);
    float r3 = v.w - __bfloat162float(h1.y);
    __nv_bfloat162 l0 = __floats2bfloat162_rn(r0, r1);
    __nv_bfloat162 l1 = __floats2bfloat162_rn(r2, r3);
    *reinterpret_cast<uint2*>(smem + off_hi) =
        make_uint2(*reinterpret_cast<const uint32_t*>(&h0), *reinterpret_cast<const uint32_t*>(&h1));
    *reinterpret_cast<uint2*>(smem + off_lo) =
        make_uint2(*reinterpret_cast<const uint32_t*>(&l0), *reinterpret_cast<const uint32_t*>(&l1));
}

// ---------------- tensor GEMM: C[m,n] = sum_k A[m,k] * W[n,k]  (split-bf16, fp32 acc) ----------------
// CTA tile 128(m) x 64(n), 8 warps in 4(m) x 2(n), warp tile 32x32. K chunks of 128.
template<bool ACCUM, bool RELU, bool BIAS, bool EXTRA>
__global__ __launch_bounds__(256, 2)
void tc_gemm(const float* __restrict__ A, int lda,
             const float* __restrict__ W, int ldw,
             const float* __restrict__ bias,
             const float* __restrict__ extra,
             const float* __restrict__ epsp,
             float* __restrict__ C, int ldc, int M, int K)
{
    extern __shared__ char smem[];
    const uint32_t sb = smem_u32(smem);
    const int tid  = threadIdx.x;
    const int wid  = tid >> 5;
    const int lane = tid & 31;
    const int bm   = blockIdx.x * 128;
    const int bn   = blockIdx.y * 64;
    const int wm   = (wid >> 1) * 32;   // warp row offset (4 groups of 32)
    const int wn   = (wid & 1) * 32;    // warp col offset (2 groups of 32)

    float acc[2][4][4];                 // [mi][nj][frag]
#pragma unroll
    for (int i = 0; i < 2; i++)
#pragma unroll
        for (int j = 0; j < 4; j++)
#pragma unroll
            for (int f = 0; f < 4; f++) acc[i][j][f] = 0.f;

    const int g  = lane >> 3;           // ldmatrix address group 0..3
    const int lr = lane & 7;
    const uint32_t aRowPart = (uint32_t)((wm + (g & 1) * 8 + lr) * SROW + (g >> 1) * 8);
    const uint32_t bRowPart = (uint32_t)((wn + (g >> 1) * 8 + lr) * SROW + (g & 1) * 8);

    for (int kb = 0; kb < K; kb += 128) {
        if (kb) __syncthreads();
        // A: 128 rows x 128 cols
#pragma unroll 4
        for (int it = tid; it < 4096; it += 256) {
            const int r = it >> 5;
            const int c = (it & 31) << 2;
            const uint32_t off = (uint32_t)(r * SROW + c) * 2;
            float4 va = make_float4(0.f, 0.f, 0.f, 0.f);
            const int am = bm + r;
            if (am < M) va = *reinterpret_cast<const float4*>(A + (size_t)am * lda + kb + c);
            split_store(smem, OFF_AHI + off, OFF_ALO + off, va);
        }
        // W: 64 rows x 128 cols
#pragma unroll 2
        for (int it = tid; it < 2048; it += 256) {
            const int r = it >> 5;
            const int c = (it & 31) << 2;
            const uint32_t off = (uint32_t)(r * SROW + c) * 2;
            const float4 vw = *reinterpret_cast<const float4*>(W + (size_t)(bn + r) * ldw + kb + c);
            split_store(smem, OFF_WHI + off, OFF_WLO + off, vw);
        }
        __syncthreads();

#pragma unroll
        for (int ks = 0; ks < 8; ks++) {
            const uint32_t kk = ks * 16;
            uint32_t ah[2][4], al[2][4];
            uint32_t bh[4][2], bl[4][2];
#pragma unroll
            for (int i = 0; i < 2; i++) {
                const uint32_t ao = (aRowPart + (uint32_t)(i * 16) * SROW + kk) * 2;
                ldsm_x4(ah[i][0], ah[i][1], ah[i][2], ah[i][3], sb + OFF_AHI + ao);
                ldsm_x4(al[i][0], al[i][1], al[i][2], al[i][3], sb + OFF_ALO + ao);
            }
            {
                const uint32_t bo0 = (bRowPart + kk) * 2;
                const uint32_t bo1 = (bRowPart + (uint32_t)(16 * SROW) + kk) * 2;
                ldsm_x4(bh[0][0], bh[0][1], bh[1][0], bh[1][1], sb + OFF_WHI + bo0);
                ldsm_x4(bh[2][0], bh[2][1], bh[3][0], bh[3][1], sb + OFF_WHI + bo1);
                ldsm_x4(bl[0][0], bl[0][1], bl[1][0], bl[1][1], sb + OFF_WLO + bo0);
                ldsm_x4(bl[2][0], bl[2][1], bl[3][0], bl[3][1], sb + OFF_WLO + bo1);
            }
#pragma unroll
            for (int i = 0; i < 2; i++)
#pragma unroll
                for (int j = 0; j < 4; j++) {
                    mma_bf16(acc[i][j], ah[i], bh[j][0], bh[j][1]);   // hi * hi
                    mma_bf16(acc[i][j], ah[i], bl[j][0], bl[j][1]);   // hi * lo
                    mma_bf16(acc[i][j], al[i], bh[j][0], bh[j][1]);   // lo * hi
                }
        }
    }

    // ---- epilogue ----
    const float epsv = EXTRA ? __ldg(epsp) : 0.f;
    const int qr = lane >> 2;
    const int qc = (lane & 3) * 2;
#pragma unroll
    for (int i = 0; i < 2; i++) {
        const int r0 = bm + wm + i * 16 + qr;
#pragma unroll
        for (int j = 0; j < 4; j++) {
            const int col = bn + wn + j * 8 + qc;
#pragma unroll
            for (int half = 0; half < 2; half++) {
                const int rr = r0 + half * 8;
                if (rr < M) {
                    float vx = acc[i][j][half * 2 + 0];
                    float vy = acc[i][j][half * 2 + 1];
                    if (BIAS) {
                        const float2 b2 = *reinterpret_cast<const float2*>(bias + col);
                        vx += b2.x; vy += b2.y;
                    }
                    float* cp = C + (size_t)rr * ldc + col;
                    if (ACCUM) {
                        const float2 c2 = *reinterpret_cast<const float2*>(cp);
                        vx += c2.x; vy += c2.y;
                    }
                    if (EXTRA) {
                        const float2 e2 = *reinterpret_cast<const float2*>(extra + (size_t)rr * ldc + col);
                        vx = fmaf(epsv, e2.x, vx); vy = fmaf(epsv, e2.y, vy);
                    }
                    if (RELU) { vx = fmaxf(vx, 0.f); vy = fmaxf(vy, 0.f); }
                    *reinterpret_cast<float2*>(cp) = make_float2(vx, vy);
                }
            }
        }
    }
}

// ================= CSR build =================
__global__ void k_zero(int M) {
    int i = blockIdx.x * blockDim.x + threadIdx.x;
    if (i < M) g_deg[i] = 0;
    if (i < 1024) g_stats[i] = 0.f;
}

__global__ void k_hist(const int* __restrict__ edges, int E) {
    int i = blockIdx.x * blockDim.x + threadIdx.x;
    if (i < E) atomicAdd(&g_deg[__ldg(edges + E + i)], 1);
}

// block-local exclusive scan over 512 nodes, 512 threads/block
__global__ void k_scan1(int M) {
    __shared__ int s[512];
    const int tid = threadIdx.x;
    const int i = blockIdx.x * 512 + tid;
    const int v = (i < M) ? g_deg[i] : 0;
    s[tid] = v;
    __syncthreads();
#pragma unroll
    for (int d = 1; d < 512; d <<= 1) {
        int u = (tid >= d) ? s[tid - d] : 0;
        __syncthreads();
        s[tid] += u;
        __syncthreads();
    }
    if (i < M) g_off[i] = s[tid] - v;          // local exclusive
    if (tid == 511) g_part[blockIdx.x] = s[511];
}

__global__ void k_scan2(int nblk) {
    __shared__ int s[1024];
    const int t = threadIdx.x;
    const int v = (t < nblk) ? g_part[t] : 0;
    s[t] = v;
    __syncthreads();
#pragma unroll
    for (int d = 1; d < 1024; d <<= 1) {
        int u = (t >= d) ? s[t - d] : 0;
        __syncthreads();
        s[t] += u;
        __syncthreads();
    }
    if (t < nblk) g_part[t] = s[t] - v;        // exclusive block bases
}

__global__ void k_scan3(int M) {
    int i = blockIdx.x * blockDim.x + threadIdx.x;
    if (i < M) {
        int o = g_off[i] + g_part[i >> 9];
        g_off[i] = o;
        g_cur[i] = o;
    }
}

__global__ void k_place(const int* __restrict__ edges, int E) {
    int i = blockIdx.x * blockDim.x + threadIdx.x;
    if (i < E) {
        const int s = __ldg(edges + i);
        const int d = __ldg(edges + E + i);
        const int pos = atomicAdd(&g_cur[d], 1);
        g_ssrc[pos] = s;
    }
}

// ================= aggregation: warp per node, no atomics =================
__global__ __launch_bounds__(256)
void k_aggregate(const float* __restrict__ x, int M)
{
    const int w = blockIdx.x * 8 + (threadIdx.x >> 5);
    const int lane = threadIdx.x & 31;
    if (w >= M) return;
    const int beg = g_deg ? g_off[w] : 0;
    const int deg = g_deg[w];
    const int co = lane * 4;

    float4 sum = make_float4(0.f, 0.f, 0.f, 0.f);
    float4 mx  = make_float4(-INFINITY, -INFINITY, -INFINITY, -INFINITY);

    int e = 0;
    for (; e + 2 <= deg; e += 2) {
        const int s0 = __ldg(g_ssrc + beg + e);
        const int s1 = __ldg(g_ssrc + beg + e + 1);
        const float4 a0 = *reinterpret_cast<const float4*>(x    + (size_t)s0 * DIM + co);
        const float4 m0 = *reinterpret_cast<const float4*>(g_xi + (size_t)s0 * DIM + co);
        const float4 a1 = *reinterpret_cast<const float4*>(x    + (size_t)s1 * DIM + co);
        const float4 m1 = *reinterpret_cast<const float4*>(g_xi + (size_t)s1 * DIM + co);
        sum.x += a0.x + a1.x; sum.y += a0.y + a1.y;
        sum.z += a0.z + a1.z; sum.w += a0.w + a1.w;
        mx.x = fmaxf(mx.x, fmaxf(m0.x, m1.x)); mx.y = fmaxf(mx.y, fmaxf(m0.y, m1.y));
        mx.z = fmaxf(mx.z, fmaxf(m0.z, m1.z)); mx.w = fmaxf(mx.w, fmaxf(m0.w, m1.w));
    }
    if (e < deg) {
        const int s0 = __ldg(g_ssrc + beg + e);
        const float4 a0 = *reinterpret_cast<const float4*>(x    + (size_t)s0 * DIM + co);
        const float4 m0 = *reinterpret_cast<const float4*>(g_xi + (size_t)s0 * DIM + co);
        sum.x += a0.x; sum.y += a0.y; sum.z += a0.z; sum.w += a0.w;
        mx.x = fmaxf(mx.x, m0.x); mx.y = fmaxf(mx.y, m0.y);
        mx.z = fmaxf(mx.z, m0.z); mx.w = fmaxf(mx.w, m0.w);
    }
    if (deg == 0) mx = make_float4(0.f, 0.f, 0.f, 0.f);

    *reinterpret_cast<float4*>(g_aggsum + (size_t)w * DIM + co) = sum;
    *reinterpret_cast<float4*>(g_aggmax + (size_t)w * DIM + co) = mx;
}

// ---------------- GRU elementwise ----------------
__global__ void gru_kernel(const float* __restrict__ x, int M) {
    const size_t i = (size_t)blockIdx.x * blockDim.x + threadIdx.x;
    if (i >= (size_t)M * DIM) return;
    const size_t m = i >> 7;
    const int    d = (int)(i & 127);
    const size_t b = m * (3 * DIM);
    const float ir = g_gi[b + d],         hr = g_gh[b + d];
    const float iz = g_gi[b + DIM + d],   hz = g_gh[b + DIM + d];
    const float in = g_gi[b + 2*DIM + d], hn = g_gh[b + 2*DIM + d];
    const float r  = 1.f / (1.f + __expf(-(ir + hr)));
    const float z  = 1.f / (1.f + __expf(-(iz + hz)));
    const float nc = tanhf(in + r * hn);
    g_rnn[i] = (1.f - z) * nc + z * x[i];
}

// ---------------- batchnorm ----------------
__global__ void bn_stats(const float* __restrict__ out, int M) {
    const int c = threadIdx.x;   // 128 threads
    float s = 0.f, s2 = 0.f;
    for (int m = blockIdx.x; m < M; m += gridDim.x) {
        float v = out[(size_t)m * DIM + c];
        s += v; s2 += v * v;
    }
    atomicAdd(&g_stats[c], s);
    atomicAdd(&g_stats[128 + c], s2);
}

__global__ void bn_finalize(const float* __restrict__ gamma, const float* __restrict__ beta, int M) {
    const int c = threadIdx.x;   // 128 threads, 1 block
    const float invM = 1.f / (float)M;
    const float mean = g_stats[c] * invM;
    const float var  = g_stats[128 + c] * invM - mean * mean;
    const float sc   = gamma[c] * rsqrtf(var + 1e-5f);
    g_stats[256 + c] = sc;
    g_stats[384 + c] = beta[c] - mean * sc;
}

__global__ void bn_apply(float* __restrict__ out, int M) {
    const size_t i = (size_t)blockIdx.x * blockDim.x + threadIdx.x;
    if (i >= (size_t)M * DIM) return;
    const int c = (int)(i & 127);
    out[i] = out[i] * g_stats[256 + c] + g_stats[384 + c];
}

// ---------------- launcher ----------------
extern "C" void kernel_launch(void* const* d_in, const int* in_sizes, int n_in,
                              void* d_out, int out_size)
{
    const float* x       = (const float*)d_in[0];
    const int*   edges   = (const int*)  d_in[1];
    const float* W_aff   = (const float*)d_in[2];
    const float* b_aff   = (const float*)d_in[3];
    const float* W_ih    = (const float*)d_in[4];
    const float* b_ih    = (const float*)d_in[5];
    const float* W_hh    = (const float*)d_in[6];
    const float* b_hh    = (const float*)d_in[7];
    const float* W_merge = (const float*)d_in[8];
    const float* b_merge = (const float*)d_in[9];
    const float* epsp    = (const float*)d_in[10];
    const float* W1      = (const float*)d_in[11];
    const float* b1      = (const float*)d_in[12];
    const float* W2      = (const float*)d_in[13];
    const float* b2      = (const float*)d_in[14];
    const float* gamma   = (const float*)d_in[15];
    const float* beta    = (const float*)d_in[16];
    float* out = (float*)d_out;

    const int M = in_sizes[0] / DIM;
    const int E = in_sizes[1] / 2;
    const size_t ND = (size_t)M * DIM;

    void *p_xi, *p_sum, *p_max, *p_gi, *p_gh, *p_rnn, *p_h, *p_t1;
    cudaGetSymbolAddress(&p_xi,  g_xi);
    cudaGetSymbolAddress(&p_sum, g_aggsum);
    cudaGetSymbolAddress(&p_max, g_aggmax);
    cudaGetSymbolAddress(&p_gi,  g_gi);
    cudaGetSymbolAddress(&p_gh,  g_gh);
    cudaGetSymbolAddress(&p_rnn, g_rnn);
    cudaGetSymbolAddress(&p_h,   g_h);
    cudaGetSymbolAddress(&p_t1,  g_t1);
    float* xi  = (float*)p_xi;   float* aggsum = (float*)p_sum;
    float* aggmax = (float*)p_max;
    float* gi  = (float*)p_gi;   float* gh  = (float*)p_gh;
    float* rnn = (float*)p_rnn;  float* h   = (float*)p_h;
    float* t1  = (float*)p_t1;

    cudaFuncSetAttribute(tc_gemm<false,false,true, false>, cudaFuncAttributeMaxDynamicSharedMemorySize, TCG_SMEM);
    cudaFuncSetAttribute(tc_gemm<false,false,false,false>, cudaFuncAttributeMaxDynamicSharedMemorySize, TCG_SMEM);
    cudaFuncSetAttribute(tc_gemm<true, false,true, true >, cudaFuncAttributeMaxDynamicSharedMemorySize, TCG_SMEM);
    cudaFuncSetAttribute(tc_gemm<false,true, true, false>, cudaFuncAttributeMaxDynamicSharedMemorySize, TCG_SMEM);

    const int mtiles = (M + 127) / 128;
    const int nd_blk = (int)((ND + 255) / 256);
    const int e_blk  = (E + 255) / 256;
    const int m_blk  = (M + 255) / 256;
    const int nscan  = (M + 511) / 512;

    // ---- CSR build (also zeroes bn stats) ----
    k_zero <<<m_blk, 256>>>(M);
    k_hist <<<e_blk, 256>>>(edges, E);
    k_scan1<<<nscan, 512>>>(M);
    k_scan2<<<1, 1024>>>(nscan);
    k_scan3<<<m_blk, 256>>>(M);
    k_place<<<e_blk, 256>>>(edges, E);

    // ---- xi = x @ W_aff^T + b_aff ----
    tc_gemm<false,false,true,false><<<dim3(mtiles,2), 256, TCG_SMEM>>>(
        x, DIM, W_aff, DIM, b_aff, nullptr, nullptr, xi, DIM, M, DIM);

    // ---- aggregate: sum(x[src]) and max(xi[src]) per node, no atomics ----
    k_aggregate<<<(M + 7) / 8, 256>>>(x, M);

    // ---- gi = agg_max @ W_ih^T + b_ih  (N = 384) ----
    tc_gemm<false,false,true,false><<<dim3(mtiles,6), 256, TCG_SMEM>>>(
        aggmax, DIM, W_ih, DIM, b_ih, nullptr, nullptr, gi, 3*DIM, M, DIM);

    // ---- gh = x @ W_hh^T + b_hh       (N = 384) ----
    tc_gemm<false,false,true,false><<<dim3(mtiles,6), 256, TCG_SMEM>>>(
        x, DIM, W_hh, DIM, b_hh, nullptr, nullptr, gh, 3*DIM, M, DIM);

    // ---- GRU elementwise -> rnn ----
    gru_kernel<<<nd_blk, 256>>>(x, M);

    // ---- h = agg_sum @ W_merge[:, :128]^T ----
    tc_gemm<false,false,false,false><<<dim3(mtiles,2), 256, TCG_SMEM>>>(
        aggsum, DIM, W_merge, 2*DIM, nullptr, nullptr, nullptr, h, DIM, M, DIM);

    // ---- h += rnn @ W_merge[:, 128:]^T + b_merge + eps * x ----
    tc_gemm<true,false,true,true><<<dim3(mtiles,2), 256, TCG_SMEM>>>(
        rnn, DIM, W_merge + DIM, 2*DIM, b_merge, x, epsp, h, DIM, M, DIM);

    // ---- t1 = relu(h @ W1^T + b1)     (N = 256) ----
    tc_gemm<false,true,true,false><<<dim3(mtiles,4), 256, TCG_SMEM>>>(
        h, DIM, W1, DIM, b1, nullptr, nullptr, t1, HID, M, DIM);

    // ---- out = relu(t1 @ W2^T + b2)   (K = 256) ----
    tc_gemm<false,true,true,false><<<dim3(mtiles,2), 256, TCG_SMEM>>>(
        t1, HID, W2, HID, b2, nullptr, nullptr, out, DIM, M, HID);

    // ---- batchnorm ----
    bn_stats<<<512, 128>>>(out, M);
    bn_finalize<<<1, 128>>>(gamma, beta, M);
    bn_apply<<<nd_blk, 256>>>(out, M);
}

// round 6
// speedup vs baseline: 3.1172x; 1.1269x over previous
#include <cuda_runtime.h>
#include <cuda_bf16.h>
#include <cstdint>
#include <math.h>

// ---------------- problem constants ----------------
#define MAXN   100000
#define MROUND 100096      // MAXN rounded up to 128-row tiles (pad rows readable)
#define MAXE   1600000
#define DIM    128
#define HID    256

// ---------------- scratch (static device memory; no allocation) ----------------
// fp32 intermediates
__device__ __align__(128) float g_xi  [(size_t)MROUND * DIM];
__device__ __align__(128) float g_gi  [(size_t)MROUND * 3 * DIM];
__device__ __align__(128) float g_gh  [(size_t)MROUND * 3 * DIM];
__device__ __align__(128) float g_stats[1024];
// bf16 hi/lo split intermediates
__device__ __align__(128) __nv_bfloat16 g_xh [(size_t)MROUND * DIM];
__device__ __align__(128) __nv_bfloat16 g_xl [(size_t)MROUND * DIM];
__device__ __align__(128) __nv_bfloat16 g_ash[(size_t)MROUND * DIM];
__device__ __align__(128) __nv_bfloat16 g_asl[(size_t)MROUND * DIM];
__device__ __align__(128) __nv_bfloat16 g_amh[(size_t)MROUND * DIM];
__device__ __align__(128) __nv_bfloat16 g_aml[(size_t)MROUND * DIM];
__device__ __align__(128) __nv_bfloat16 g_rnh[(size_t)MROUND * DIM];
__device__ __align__(128) __nv_bfloat16 g_rnl[(size_t)MROUND * DIM];
__device__ __align__(128) __nv_bfloat16 g_hh [(size_t)MROUND * DIM];
__device__ __align__(128) __nv_bfloat16 g_hl [(size_t)MROUND * DIM];
__device__ __align__(128) __nv_bfloat16 g_t1h[(size_t)MROUND * HID];
__device__ __align__(128) __nv_bfloat16 g_t1l[(size_t)MROUND * HID];
// weight hi/lo
__device__ __align__(128) __nv_bfloat16 g_waffh[128*128], g_waffl[128*128];
__device__ __align__(128) __nv_bfloat16 g_wihh [384*128], g_wihl [384*128];
__device__ __align__(128) __nv_bfloat16 g_whhh [384*128], g_whhl [384*128];
__device__ __align__(128) __nv_bfloat16 g_wmh  [128*256], g_wml  [128*256];
__device__ __align__(128) __nv_bfloat16 g_w1h  [256*128], g_w1l  [256*128];
__device__ __align__(128) __nv_bfloat16 g_w2h  [128*256], g_w2l  [128*256];
// CSR scratch
__device__ __align__(128) int g_deg [MAXN];
__device__ __align__(128) int g_off [MAXN];
__device__ __align__(128) int g_cur [MAXN];
__device__ __align__(128) int g_part[1024];
__device__ __align__(128) int g_ssrc[MAXE];

// ================= helpers =================
__device__ __forceinline__ uint32_t smem_u32(const void* p) {
    uint32_t a;
    asm("{ .reg .u64 t; cvta.to.shared.u64 t, %1; cvt.u32.u64 %0, t; }" : "=r"(a) : "l"(p));
    return a;
}
__device__ __forceinline__ void ldsm_x4(uint32_t& r0, uint32_t& r1, uint32_t& r2, uint32_t& r3,
                                        uint32_t addr) {
    asm volatile("ldmatrix.sync.aligned.m8n8.x4.shared.b16 {%0,%1,%2,%3}, [%4];"
                 : "=r"(r0), "=r"(r1), "=r"(r2), "=r"(r3) : "r"(addr));
}
__device__ __forceinline__ void mma_bf16(float* c, const uint32_t* a, uint32_t b0, uint32_t b1) {
    asm volatile(
        "mma.sync.aligned.m16n8k16.row.col.f32.bf16.bf16.f32 "
        "{%0,%1,%2,%3}, {%4,%5,%6,%7}, {%8,%9}, {%0,%1,%2,%3};"
        : "+f"(c[0]), "+f"(c[1]), "+f"(c[2]), "+f"(c[3])
        : "r"(a[0]), "r"(a[1]), "r"(a[2]), "r"(a[3]), "r"(b0), "r"(b1));
}
// split (vx, vy) -> packed bf16x2 hi / lo
__device__ __forceinline__ void split2(float vx, float vy, uint32_t& hi, uint32_t& lo) {
    __nv_bfloat162 h = __floats2bfloat162_rn(vx, vy);
    float rx = vx - __bfloat162float(h.x);
    float ry = vy - __bfloat162float(h.y);
    __nv_bfloat162 l = __floats2bfloat162_rn(rx, ry);
    hi = *reinterpret_cast<const uint32_t*>(&h);
    lo = *reinterpret_cast<const uint32_t*>(&l);
}

// ---------------- smem layout ----------------
#define SROW      136                      // bf16 elements per row (128 + 8 pad)
#define ATILE_B   (128 * SROW * 2)         // 34816
#define WTILE_B   (64  * SROW * 2)         // 17408
#define OFF_AHI   0
#define OFF_ALO   (ATILE_B)
#define OFF_WHI   (2 * ATILE_B)
#define OFF_WLO   (2 * ATILE_B + WTILE_B)
#define TCG_SMEM  (2 * ATILE_B + 2 * WTILE_B)   // 104448 -> 2 CTAs/SM

// ---------------- tensor GEMM: C[m, ny*64+n'] = sum_k A[m,k] * W[n,k] ----------------
// A resident across N subtiles when KC==1. split-bf16 inputs, fp32 acc.
// CTA: 128 rows x (NYT x 64) cols; 8 warps 4(m) x 2(n); K chunks of 128.
template<bool RELU, bool BIAS, bool EXTRA, bool OUTHL>
__global__ __launch_bounds__(256, 2)
void tc_gemm(const __nv_bfloat16* __restrict__ a0h, const __nv_bfloat16* __restrict__ a0l,
             const __nv_bfloat16* __restrict__ a1h, const __nv_bfloat16* __restrict__ a1l,
             int lda,
             const __nv_bfloat16* __restrict__ wh, const __nv_bfloat16* __restrict__ wl,
             int ldw,
             const float* __restrict__ bias, const float* __restrict__ extra,
             const float* __restrict__ epsp,
             float* __restrict__ Cf,
             __nv_bfloat16* __restrict__ Chh, __nv_bfloat16* __restrict__ Cll,
             int ldc, int M, int KC, int NYT)
{
    extern __shared__ char smem[];
    const uint32_t sb = smem_u32(smem);
    const int tid  = threadIdx.x;
    const int wid  = tid >> 5;
    const int lane = tid & 31;
    const int bm   = blockIdx.x * 128;
    const int wm   = (wid >> 1) * 32;
    const int wn   = (wid & 1) * 32;

    const int g  = lane >> 3;
    const int lr = lane & 7;
    const uint32_t aRowPart = (uint32_t)((wm + (g & 1) * 8 + lr) * SROW + (g >> 1) * 8);
    const uint32_t bRowPart = (uint32_t)((wn + (g >> 1) * 8 + lr) * SROW + (g & 1) * 8);

    const float epsv = EXTRA ? __ldg(epsp) : 0.f;
    const int qr = lane >> 2;
    const int qc = (lane & 3) * 2;

    for (int ny = 0; ny < NYT; ny++) {
        float acc[2][4][4];
#pragma unroll
        for (int i = 0; i < 2; i++)
#pragma unroll
            for (int j = 0; j < 4; j++)
#pragma unroll
                for (int f = 0; f < 4; f++) acc[i][j][f] = 0.f;

        for (int kc = 0; kc < KC; kc++) {
            if (ny || kc) __syncthreads();
            // ---- load A chunk (resident across ny when KC==1) ----
            if (KC > 1 || ny == 0) {
                const __nv_bfloat16* ah = kc ? a1h : a0h;
                const __nv_bfloat16* al = kc ? a1l : a0l;
#pragma unroll 4
                for (int it = tid; it < 2048; it += 256) {
                    const int r = it >> 4;
                    const int c = (it & 15) * 8;
                    const uint32_t off = (uint32_t)(r * SROW + c) * 2;
                    const size_t ga = (size_t)(bm + r) * lda + c;
                    *reinterpret_cast<uint4*>(smem + OFF_AHI + off) =
                        *reinterpret_cast<const uint4*>(ah + ga);
                    *reinterpret_cast<uint4*>(smem + OFF_ALO + off) =
                        *reinterpret_cast<const uint4*>(al + ga);
                }
            }
            // ---- load W subtile (64 rows x 128 cols) ----
#pragma unroll 2
            for (int it = tid; it < 1024; it += 256) {
                const int r = it >> 4;
                const int c = (it & 15) * 8;
                const uint32_t off = (uint32_t)(r * SROW + c) * 2;
                const size_t gw = (size_t)(ny * 64 + r) * ldw + kc * 128 + c;
                *reinterpret_cast<uint4*>(smem + OFF_WHI + off) =
                    *reinterpret_cast<const uint4*>(wh + gw);
                *reinterpret_cast<uint4*>(smem + OFF_WLO + off) =
                    *reinterpret_cast<const uint4*>(wl + gw);
            }
            __syncthreads();

#pragma unroll
            for (int ks = 0; ks < 8; ks++) {
                const uint32_t kk = ks * 16;
                uint32_t ah_[2][4], al_[2][4];
                uint32_t bh_[4][2], bl_[4][2];
#pragma unroll
                for (int i = 0; i < 2; i++) {
                    const uint32_t ao = (aRowPart + (uint32_t)(i * 16) * SROW + kk) * 2;
                    ldsm_x4(ah_[i][0], ah_[i][1], ah_[i][2], ah_[i][3], sb + OFF_AHI + ao);
                    ldsm_x4(al_[i][0], al_[i][1], al_[i][2], al_[i][3], sb + OFF_ALO + ao);
                }
                {
                    const uint32_t bo0 = (bRowPart + kk) * 2;
                    const uint32_t bo1 = (bRowPart + (uint32_t)(16 * SROW) + kk) * 2;
                    ldsm_x4(bh_[0][0], bh_[0][1], bh_[1][0], bh_[1][1], sb + OFF_WHI + bo0);
                    ldsm_x4(bh_[2][0], bh_[2][1], bh_[3][0], bh_[3][1], sb + OFF_WHI + bo1);
                    ldsm_x4(bl_[0][0], bl_[0][1], bl_[1][0], bl_[1][1], sb + OFF_WLO + bo0);
                    ldsm_x4(bl_[2][0], bl_[2][1], bl_[3][0], bl_[3][1], sb + OFF_WLO + bo1);
                }
#pragma unroll
                for (int i = 0; i < 2; i++)
#pragma unroll
                    for (int j = 0; j < 4; j++) {
                        mma_bf16(acc[i][j], ah_[i], bh_[j][0], bh_[j][1]);   // hi*hi
                        mma_bf16(acc[i][j], ah_[i], bl_[j][0], bl_[j][1]);   // hi*lo
                        mma_bf16(acc[i][j], al_[i], bh_[j][0], bh_[j][1]);   // lo*hi
                    }
            }
        }

        // ---- epilogue for this N subtile (registers -> gmem; no smem use) ----
#pragma unroll
        for (int i = 0; i < 2; i++) {
#pragma unroll
            for (int j = 0; j < 4; j++) {
                const int col = ny * 64 + wn + j * 8 + qc;
#pragma unroll
                for (int half = 0; half < 2; half++) {
                    const int rr = bm + wm + i * 16 + qr + half * 8;
                    if (rr < M) {
                        float vx = acc[i][j][half * 2 + 0];
                        float vy = acc[i][j][half * 2 + 1];
                        if (BIAS) {
                            const float2 b2 = *reinterpret_cast<const float2*>(bias + col);
                            vx += b2.x; vy += b2.y;
                        }
                        if (EXTRA) {
                            const float2 e2 = *reinterpret_cast<const float2*>(extra + (size_t)rr * ldc + col);
                            vx = fmaf(epsv, e2.x, vx); vy = fmaf(epsv, e2.y, vy);
                        }
                        if (RELU) { vx = fmaxf(vx, 0.f); vy = fmaxf(vy, 0.f); }
                        if (OUTHL) {
                            uint32_t hi, lo;
                            split2(vx, vy, hi, lo);
                            *reinterpret_cast<uint32_t*>(Chh + (size_t)rr * ldc + col) = hi;
                            *reinterpret_cast<uint32_t*>(Cll + (size_t)rr * ldc + col) = lo;
                        } else {
                            *reinterpret_cast<float2*>(Cf + (size_t)rr * ldc + col) = make_float2(vx, vy);
                        }
                    }
                }
            }
        }
    }
}

// ================= split kernels =================
__global__ void k_split(const float* __restrict__ src, __nv_bfloat16* __restrict__ dh,
                        __nv_bfloat16* __restrict__ dl, int n4) {
    const int i = blockIdx.x * blockDim.x + threadIdx.x;
    if (i >= n4) return;
    const float4 v = *reinterpret_cast<const float4*>(src + (size_t)i * 4);
    uint32_t h0, l0, h1, l1;
    split2(v.x, v.y, h0, l0);
    split2(v.z, v.w, h1, l1);
    *reinterpret_cast<uint2*>(dh + (size_t)i * 4) = make_uint2(h0, h1);
    *reinterpret_cast<uint2*>(dl + (size_t)i * 4) = make_uint2(l0, l1);
}

// ================= CSR build =================
__global__ void k_zero(int M) {
    int i = blockIdx.x * blockDim.x + threadIdx.x;
    if (i < M) g_deg[i] = 0;
    if (i < 1024) g_stats[i] = 0.f;
}
__global__ void k_hist(const int* __restrict__ edges, int E) {
    int i = blockIdx.x * blockDim.x + threadIdx.x;
    if (i < E) atomicAdd(&g_deg[__ldg(edges + E + i)], 1);
}
__global__ void k_scan1(int M) {
    __shared__ int s[512];
    const int tid = threadIdx.x;
    const int i = blockIdx.x * 512 + tid;
    const int v = (i < M) ? g_deg[i] : 0;
    s[tid] = v;
    __syncthreads();
#pragma unroll
    for (int d = 1; d < 512; d <<= 1) {
        int u = (tid >= d) ? s[tid - d] : 0;
        __syncthreads();
        s[tid] += u;
        __syncthreads();
    }
    if (i < M) g_off[i] = s[tid] - v;
    if (tid == 511) g_part[blockIdx.x] = s[511];
}
__global__ void k_scan2(int nblk) {
    __shared__ int s[1024];
    const int t = threadIdx.x;
    const int v = (t < nblk) ? g_part[t] : 0;
    s[t] = v;
    __syncthreads();
#pragma unroll
    for (int d = 1; d < 1024; d <<= 1) {
        int u = (t >= d) ? s[t - d] : 0;
        __syncthreads();
        s[t] += u;
        __syncthreads();
    }
    if (t < nblk) g_part[t] = s[t] - v;
}
__global__ void k_scan3(int M) {
    int i = blockIdx.x * blockDim.x + threadIdx.x;
    if (i < M) {
        int o = g_off[i] + g_part[i >> 9];
        g_off[i] = o;
        g_cur[i] = o;
    }
}
__global__ void k_place(const int* __restrict__ edges, int E) {
    int i = blockIdx.x * blockDim.x + threadIdx.x;
    if (i < E) {
        const int s = __ldg(edges + i);
        const int d = __ldg(edges + E + i);
        const int pos = atomicAdd(&g_cur[d], 1);
        g_ssrc[pos] = s;
    }
}

// ================= aggregation: warp per node, no atomics; writes hi/lo splits =================
__global__ __launch_bounds__(256)
void k_aggregate(const float* __restrict__ x, int M)
{
    const int w = blockIdx.x * 8 + (threadIdx.x >> 5);
    const int lane = threadIdx.x & 31;
    if (w >= M) return;
    const int beg = g_off[w];
    const int deg = g_deg[w];
    const int co = lane * 4;

    float4 sum = make_float4(0.f, 0.f, 0.f, 0.f);
    float4 mx  = make_float4(-INFINITY, -INFINITY, -INFINITY, -INFINITY);

    int e = 0;
    for (; e + 2 <= deg; e += 2) {
        const int s0 = __ldg(g_ssrc + beg + e);
        const int s1 = __ldg(g_ssrc + beg + e + 1);
        const float4 a0 = *reinterpret_cast<const float4*>(x    + (size_t)s0 * DIM + co);
        const float4 m0 = *reinterpret_cast<const float4*>(g_xi + (size_t)s0 * DIM + co);
        const float4 a1 = *reinterpret_cast<const float4*>(x    + (size_t)s1 * DIM + co);
        const float4 m1 = *reinterpret_cast<const float4*>(g_xi + (size_t)s1 * DIM + co);
        sum.x += a0.x + a1.x; sum.y += a0.y + a1.y;
        sum.z += a0.z + a1.z; sum.w += a0.w + a1.w;
        mx.x = fmaxf(mx.x, fmaxf(m0.x, m1.x)); mx.y = fmaxf(mx.y, fmaxf(m0.y, m1.y));
        mx.z = fmaxf(mx.z, fmaxf(m0.z, m1.z)); mx.w = fmaxf(mx.w, fmaxf(m0.w, m1.w));
    }
    if (e < deg) {
        const int s0 = __ldg(g_ssrc + beg + e);
        const float4 a0 = *reinterpret_cast<const float4*>(x    + (size_t)s0 * DIM + co);
        const float4 m0 = *reinterpret_cast<const float4*>(g_xi + (size_t)s0 * DIM + co);
        sum.x += a0.x; sum.y += a0.y; sum.z += a0.z; sum.w += a0.w;
        mx.x = fmaxf(mx.x, m0.x); mx.y = fmaxf(mx.y, m0.y);
        mx.z = fmaxf(mx.z, m0.z); mx.w = fmaxf(mx.w, m0.w);
    }
    if (deg == 0) mx = make_float4(0.f, 0.f, 0.f, 0.f);

    const size_t o = (size_t)w * DIM + co;
    uint32_t h0, l0, h1, l1;
    split2(sum.x, sum.y, h0, l0);
    split2(sum.z, sum.w, h1, l1);
    *reinterpret_cast<uint2*>(g_ash + o) = make_uint2(h0, h1);
    *reinterpret_cast<uint2*>(g_asl + o) = make_uint2(l0, l1);
    split2(mx.x, mx.y, h0, l0);
    split2(mx.z, mx.w, h1, l1);
    *reinterpret_cast<uint2*>(g_amh + o) = make_uint2(h0, h1);
    *reinterpret_cast<uint2*>(g_aml + o) = make_uint2(l0, l1);
}

// ---------------- GRU elementwise (2 elems/thread), writes rnn hi/lo ----------------
__global__ void gru_kernel(const float* __restrict__ x, int M) {
    const size_t p = (size_t)blockIdx.x * blockDim.x + threadIdx.x;
    if (p >= (size_t)M * DIM / 2) return;
    const size_t i = p * 2;
    const size_t m = i >> 7;
    const int    d = (int)(i & 127);
    const size_t b = m * (3 * DIM);
    const float2 ir = *reinterpret_cast<const float2*>(g_gi + b + d);
    const float2 hr = *reinterpret_cast<const float2*>(g_gh + b + d);
    const float2 iz = *reinterpret_cast<const float2*>(g_gi + b + DIM + d);
    const float2 hz = *reinterpret_cast<const float2*>(g_gh + b + DIM + d);
    const float2 in = *reinterpret_cast<const float2*>(g_gi + b + 2*DIM + d);
    const float2 hn = *reinterpret_cast<const float2*>(g_gh + b + 2*DIM + d);
    const float2 xv = *reinterpret_cast<const float2*>(x + i);
    const float r0 = 1.f / (1.f + __expf(-(ir.x + hr.x)));
    const float r1 = 1.f / (1.f + __expf(-(ir.y + hr.y)));
    const float z0 = 1.f / (1.f + __expf(-(iz.x + hz.x)));
    const float z1 = 1.f / (1.f + __expf(-(iz.y + hz.y)));
    const float n0 = tanhf(in.x + r0 * hn.x);
    const float n1 = tanhf(in.y + r1 * hn.y);
    const float v0 = (1.f - z0) * n0 + z0 * xv.x;
    const float v1 = (1.f - z1) * n1 + z1 * xv.y;
    uint32_t hi, lo;
    split2(v0, v1, hi, lo);
    *reinterpret_cast<uint32_t*>(g_rnh + i) = hi;
    *reinterpret_cast<uint32_t*>(g_rnl + i) = lo;
}

// ---------------- batchnorm ----------------
__global__ void bn_stats(const float* __restrict__ out, int M) {
    const int c = threadIdx.x;
    float s = 0.f, s2 = 0.f;
    for (int m = blockIdx.x; m < M; m += gridDim.x) {
        float v = out[(size_t)m * DIM + c];
        s += v; s2 += v * v;
    }
    atomicAdd(&g_stats[c], s);
    atomicAdd(&g_stats[128 + c], s2);
}
__global__ void bn_finalize(const float* __restrict__ gamma, const float* __restrict__ beta, int M) {
    const int c = threadIdx.x;
    const float invM = 1.f / (float)M;
    const float mean = g_stats[c] * invM;
    const float var  = g_stats[128 + c] * invM - mean * mean;
    const float sc   = gamma[c] * rsqrtf(var + 1e-5f);
    g_stats[256 + c] = sc;
    g_stats[384 + c] = beta[c] - mean * sc;
}
__global__ void bn_apply(float* __restrict__ out, int M) {
    const size_t i = (size_t)blockIdx.x * blockDim.x + threadIdx.x;
    if (i >= (size_t)M * DIM) return;
    const int c = (int)(i & 127);
    out[i] = out[i] * g_stats[256 + c] + g_stats[384 + c];
}

// ---------------- launcher ----------------
extern "C" void kernel_launch(void* const* d_in, const int* in_sizes, int n_in,
                              void* d_out, int out_size)
{
    const float* x       = (const float*)d_in[0];
    const int*   edges   = (const int*)  d_in[1];
    const float* W_aff   = (const float*)d_in[2];
    const float* b_aff   = (const float*)d_in[3];
    const float* W_ih    = (const float*)d_in[4];
    const float* b_ih    = (const float*)d_in[5];
    const float* W_hh    = (const float*)d_in[6];
    const float* b_hh    = (const float*)d_in[7];
    const float* W_merge = (const float*)d_in[8];
    const float* b_merge = (const float*)d_in[9];
    const float* epsp    = (const float*)d_in[10];
    const float* W1      = (const float*)d_in[11];
    const float* b1      = (const float*)d_in[12];
    const float* W2      = (const float*)d_in[13];
    const float* b2      = (const float*)d_in[14];
    const float* gamma   = (const float*)d_in[15];
    const float* beta    = (const float*)d_in[16];
    float* out = (float*)d_out;

    const int M = in_sizes[0] / DIM;
    const int E = in_sizes[1] / 2;
    const size_t ND = (size_t)M * DIM;

    // symbol addresses
    void *pp;
    cudaGetSymbolAddress(&pp, g_xi);   float* xi = (float*)pp;
    cudaGetSymbolAddress(&pp, g_gi);   float* gi = (float*)pp;
    cudaGetSymbolAddress(&pp, g_gh);   float* gh = (float*)pp;
    cudaGetSymbolAddress(&pp, g_xh);   __nv_bfloat16* xh  = (__nv_bfloat16*)pp;
    cudaGetSymbolAddress(&pp, g_xl);   __nv_bfloat16* xl  = (__nv_bfloat16*)pp;
    cudaGetSymbolAddress(&pp, g_ash);  __nv_bfloat16* ash = (__nv_bfloat16*)pp;
    cudaGetSymbolAddress(&pp, g_asl);  __nv_bfloat16* asl = (__nv_bfloat16*)pp;
    cudaGetSymbolAddress(&pp, g_amh);  __nv_bfloat16* amh = (__nv_bfloat16*)pp;
    cudaGetSymbolAddress(&pp, g_aml);  __nv_bfloat16* aml = (__nv_bfloat16*)pp;
    cudaGetSymbolAddress(&pp, g_rnh);  __nv_bfloat16* rnh = (__nv_bfloat16*)pp;
    cudaGetSymbolAddress(&pp, g_rnl);  __nv_bfloat16* rnl = (__nv_bfloat16*)pp;
    cudaGetSymbolAddress(&pp, g_hh);   __nv_bfloat16* hh  = (__nv_bfloat16*)pp;
    cudaGetSymbolAddress(&pp, g_hl);   __nv_bfloat16* hl  = (__nv_bfloat16*)pp;
    cudaGetSymbolAddress(&pp, g_t1h);  __nv_bfloat16* t1h = (__nv_bfloat16*)pp;
    cudaGetSymbolAddress(&pp, g_t1l);  __nv_bfloat16* t1l = (__nv_bfloat16*)pp;
    cudaGetSymbolAddress(&pp, g_waffh); __nv_bfloat16* waffh = (__nv_bfloat16*)pp;
    cudaGetSymbolAddress(&pp, g_waffl); __nv_bfloat16* waffl = (__nv_bfloat16*)pp;
    cudaGetSymbolAddress(&pp, g_wihh);  __nv_bfloat16* wihh  = (__nv_bfloat16*)pp;
    cudaGetSymbolAddress(&pp, g_wihl);  __nv_bfloat16* wihl  = (__nv_bfloat16*)pp;
    cudaGetSymbolAddress(&pp, g_whhh);  __nv_bfloat16* whhh  = (__nv_bfloat16*)pp;
    cudaGetSymbolAddress(&pp, g_whhl);  __nv_bfloat16* whhl  = (__nv_bfloat16*)pp;
    cudaGetSymbolAddress(&pp, g_wmh);   __nv_bfloat16* wmh   = (__nv_bfloat16*)pp;
    cudaGetSymbolAddress(&pp, g_wml);   __nv_bfloat16* wml   = (__nv_bfloat16*)pp;
    cudaGetSymbolAddress(&pp, g_w1h);   __nv_bfloat16* w1h   = (__nv_bfloat16*)pp;
    cudaGetSymbolAddress(&pp, g_w1l);   __nv_bfloat16* w1l   = (__nv_bfloat16*)pp;
    cudaGetSymbolAddress(&pp, g_w2h);   __nv_bfloat16* w2h   = (__nv_bfloat16*)pp;
    cudaGetSymbolAddress(&pp, g_w2l);   __nv_bfloat16* w2l   = (__nv_bfloat16*)pp;

    cudaFuncSetAttribute(tc_gemm<false,true,false,false>, cudaFuncAttributeMaxDynamicSharedMemorySize, TCG_SMEM);
    cudaFuncSetAttribute(tc_gemm<false,true,true, true >, cudaFuncAttributeMaxDynamicSharedMemorySize, TCG_SMEM);
    cudaFuncSetAttribute(tc_gemm<true, true,false,true >, cudaFuncAttributeMaxDynamicSharedMemorySize, TCG_SMEM);
    cudaFuncSetAttribute(tc_gemm<true, true,false,false>, cudaFuncAttributeMaxDynamicSharedMemorySize, TCG_SMEM);

    const int mtiles = (M + 127) / 128;
    const int nd_blk = (int)((ND + 255) / 256);
    const int e_blk  = (E + 255) / 256;
    const int m_blk  = (M + 255) / 256;
    const int nscan  = (M + 511) / 512;

    // ---- CSR build (also zeroes bn stats) ----
    k_zero <<<m_blk, 256>>>(M);
    k_hist <<<e_blk, 256>>>(edges, E);
    k_scan1<<<nscan, 512>>>(M);
    k_scan2<<<1, 1024>>>(nscan);
    k_scan3<<<m_blk, 256>>>(M);
    k_place<<<e_blk, 256>>>(edges, E);

    // ---- splits: x and all weights -> bf16 hi/lo ----
    k_split<<<(int)((ND/4 + 255) / 256), 256>>>(x, xh, xl, (int)(ND / 4));
    k_split<<<(128*128/4 + 255) / 256, 256>>>(W_aff,   waffh, waffl, 128*128/4);
    k_split<<<(384*128/4 + 255) / 256, 256>>>(W_ih,    wihh,  wihl,  384*128/4);
    k_split<<<(384*128/4 + 255) / 256, 256>>>(W_hh,    whhh,  whhl,  384*128/4);
    k_split<<<(128*256/4 + 255) / 256, 256>>>(W_merge, wmh,   wml,   128*256/4);
    k_split<<<(256*128/4 + 255) / 256, 256>>>(W1,      w1h,   w1l,   256*128/4);
    k_split<<<(128*256/4 + 255) / 256, 256>>>(W2,      w2h,   w2l,   128*256/4);

    // ---- xi = x @ W_aff^T + b_aff  (fp32 out, gathered by aggregate) ----
    tc_gemm<false,true,false,false><<<mtiles, 256, TCG_SMEM>>>(
        xh, xl, nullptr, nullptr, DIM, waffh, waffl, DIM,
        b_aff, nullptr, nullptr, xi, nullptr, nullptr, DIM, M, 1, 2);

    // ---- aggregate: sum(x[src]), max(xi[src]) -> hi/lo splits ----
    k_aggregate<<<(M + 7) / 8, 256>>>(x, M);

    // ---- gi = agg_max @ W_ih^T + b_ih  (N=384, fp32) ----
    tc_gemm<false,true,false,false><<<mtiles, 256, TCG_SMEM>>>(
        amh, aml, nullptr, nullptr, DIM, wihh, wihl, DIM,
        b_ih, nullptr, nullptr, gi, nullptr, nullptr, 3*DIM, M, 1, 6);

    // ---- gh = x @ W_hh^T + b_hh  (N=384, fp32) ----
    tc_gemm<false,true,false,false><<<mtiles, 256, TCG_SMEM>>>(
        xh, xl, nullptr, nullptr, DIM, whhh, whhl, DIM,
        b_hh, nullptr, nullptr, gh, nullptr, nullptr, 3*DIM, M, 1, 6);

    // ---- GRU -> rnn hi/lo ----
    gru_kernel<<<(int)((ND/2 + 255) / 256), 256>>>(x, M);

    // ---- h = [aggsum, rnn] @ W_merge^T + b_merge + eps*x  (K=256 fused, hi/lo out) ----
    tc_gemm<false,true,true,true><<<mtiles, 256, TCG_SMEM>>>(
        ash, asl, rnh, rnl, DIM, wmh, wml, 2*DIM,
        b_merge, x, epsp, nullptr, hh, hl, DIM, M, 2, 2);

    // ---- t1 = relu(h @ W1^T + b1)  (N=256, hi/lo out) ----
    tc_gemm<true,true,false,true><<<mtiles, 256, TCG_SMEM>>>(
        hh, hl, nullptr, nullptr, DIM, w1h, w1l, DIM,
        b1, nullptr, nullptr, nullptr, t1h, t1l, HID, M, 1, 4);

    // ---- out = relu(t1 @ W2^T + b2)  (K=256, fp32 out) ----
    tc_gemm<true,true,false,false><<<mtiles, 256, TCG_SMEM>>>(
        t1h, t1l, t1h + 128, t1l + 128, HID, w2h, w2l, 2*DIM,
        b2, nullptr, nullptr, out, nullptr, nullptr, DIM, M, 2, 2);

    // ---- batchnorm ----
    bn_stats<<<512, 128>>>(out, M);
    bn_finalize<<<1, 128>>>(gamma, beta, M);
    bn_apply<<<nd_blk, 256>>>(out, M);
}